// round 7
// baseline (speedup 1.0000x reference)
#include <cuda_runtime.h>
#include <cstdint>

// MatchSegmentation: pack gt->bitmask kernel + fused CE/argmax/dedup kernel.
// matching = argmax_g S[k,g] (log2-space CE, monotone rescale); greedy dedup.

#define KK   21            // predicted segments (== out_size)
#define EPSF 1e-6f
#define PIX  128           // pixels per tile
#define TPB  224           // 7 warps: warp w owns k in {3w,3w+1,3w+2}
#define NCTA 444           // 3 CTAs/SM on 148 SMs
#define ROWW (KK+1)
#define NENT (KK*ROWW)     // 462
#define MAXN (1<<20)

__device__ float    g_acc[NENT];     // zero at load; last CTA re-zeros each run
__device__ int      g_ctr;
__device__ uint32_t g_mask[MAXN];    // packed gt bits, rebuilt every run

// gt_instance is int32 0/1; uniform(0,1) float bits are never <= 1.
__device__ __forceinline__ bool looks_like_gt(const void* p) {
    const unsigned* u = (const unsigned*)p;
    bool r = true;
#pragma unroll
    for (int i = 0; i < 64; i++) r = r && (u[i] <= 1u);
    return r;
}

__device__ __forceinline__ void cp16(void* sdst, const void* gsrc) {
    uint32_t sa = (uint32_t)__cvta_generic_to_shared(sdst);
    asm volatile("cp.async.cg.shared.global [%0], [%1], 16;" :: "r"(sa), "l"(gsrc));
}
__device__ __forceinline__ void cp_commit() { asm volatile("cp.async.commit_group;"); }
__device__ __forceinline__ void cp_wait0()  { asm volatile("cp.async.wait_group 0;"); }

__device__ __forceinline__ float wred(float v) {
    v += __shfl_down_sync(0xffffffffu, v, 16);
    v += __shfl_down_sync(0xffffffffu, v, 8);
    v += __shfl_down_sync(0xffffffffu, v, 4);
    v += __shfl_down_sync(0xffffffffu, v, 2);
    v += __shfl_down_sync(0xffffffffu, v, 1);
    return v;
}

// ---- Kernel 1: pack gt[g][p] -> 21-bit mask per pixel (bandwidth-bound) ----
__global__ __launch_bounds__(256)
void pack_kernel(const void* __restrict__ bigA, const void* __restrict__ bigB,
                 int N, int GMAX)
{
    const bool a_is_gt = looks_like_gt(bigA);
    const int* __restrict__ gt = (const int*)(a_is_gt ? bigA : bigB);
    for (int p = blockIdx.x * blockDim.x + threadIdx.x; p < N;
         p += gridDim.x * blockDim.x) {
        uint32_t m = 0;
#pragma unroll
        for (int g = 0; g < KK; g++)
            if (g < GMAX) m |= ((uint32_t)gt[(long long)g * N + p] & 1u) << g;
        g_mask[p] = m;
    }
}

// ---- Kernel 2: fused CE accumulate + argmax + greedy dedup ----
__global__ __launch_bounds__(TPB, 3)
void match_kernel(const void* __restrict__ bigA, const void* __restrict__ bigB,
                  const int* __restrict__ gpn, float* __restrict__ out,
                  int N, int GMAX)
{
    const bool a_is_gt = looks_like_gt(bigA);
    const float* __restrict__ seg = (const float*)(a_is_gt ? bigB : bigA);

    __shared__ float    s_seg[2][PIX * KK];  // [px][k] 10.5KB each
    __shared__ uint32_t s_msk[2][PIX];       // 512B each
    __shared__ float    s_red[NENT];
    __shared__ int      s_last;

    const int tid  = threadIdx.x;
    const int lane = tid & 31;
    const int k0   = (tid >> 5) * 3;
    const long long NKll = (long long)N * KK;

    float S0[KK], S1[KK], S2[KK];
    float A0 = 0.f, A1 = 0.f, A2 = 0.f;
#pragma unroll
    for (int g = 0; g < KK; g++) { S0[g] = 0.f; S1[g] = 0.f; S2[g] = 0.f; }

    const int ntiles = (N + PIX - 1) / PIX;

    auto load_tile = [&](int tt, int b) {
        const int       base = tt * PIX;
        const long long tb   = (long long)tt * (PIX * KK);
        if (base + PIX <= N && ((N & 3) == 0)) {
#pragma unroll
            for (int j = 0; j < 3; j++) {            // 672 float4 slots of seg
                const int i = tid + j * TPB;
                cp16(&s_seg[b][i * 4], seg + tb + i * 4);
            }
            if (tid < 32)                            // 128 masks = 32 int4
                cp16(&s_msk[b][tid * 4], &g_mask[base + tid * 4]);
        } else {                                      // generic tail
            for (int i = tid; i < PIX * KK; i += TPB) {
                const long long idx = tb + i;
                s_seg[b][i] = (idx < NKll) ? seg[idx] : 0.5f;  // pad: d=0
            }
            for (int c = tid; c < PIX; c += TPB) {
                const int p = base + c;
                s_msk[b][c] = (p < N) ? g_mask[p] : 0u;
            }
        }
        cp_commit();
    };

    int  t    = blockIdx.x;
    bool have = (t < ntiles);
    int  buf  = 0;
    if (have) load_tile(t, 0);

    while (have) {
        const int  tn     = t + gridDim.x;
        const bool have_n = (tn < ntiles);

        cp_wait0();
        __syncthreads();                  // tile resident; prev compute done
        if (have_n) load_tile(tn, buf ^ 1);

#pragma unroll
        for (int q = 0; q < 4; q++) {
            const int px = q * 32 + lane;
            const int pb = px * KK;
            float d0, d1, d2;
            {
                const float s  = s_seg[buf][pb + k0];
                const float l1 = __log2f(1.0f - s + EPSF);
                d0 = __log2f(s + EPSF) - l1;  A0 += l1;
            }
            {
                const float s  = s_seg[buf][pb + k0 + 1];
                const float l1 = __log2f(1.0f - s + EPSF);
                d1 = __log2f(s + EPSF) - l1;  A1 += l1;
            }
            {
                const float s  = s_seg[buf][pb + k0 + 2];
                const float l1 = __log2f(1.0f - s + EPSF);
                d2 = __log2f(s + EPSF) - l1;  A2 += l1;
            }
            const uint32_t m = s_msk[buf][px];
#pragma unroll
            for (int g = 0; g < KK; g++) {
                const float gv = (float)((m >> g) & 1u);
                S0[g] = fmaf(gv, d0, S0[g]);
                S1[g] = fmaf(gv, d1, S1[g]);
                S2[g] = fmaf(gv, d2, S2[g]);
            }
        }

        buf ^= 1;
        t    = tn;
        have = have_n;
    }

    // ---- warp reduce (lanes = pixels) -> atomic accumulate ----
#pragma unroll
    for (int g = 0; g < KK; g++) {
        float v0 = wred(S0[g]), v1 = wred(S1[g]), v2 = wred(S2[g]);
        if (lane == 0) {
            atomicAdd(&g_acc[(k0    ) * ROWW + g], v0);
            atomicAdd(&g_acc[(k0 + 1) * ROWW + g], v1);
            atomicAdd(&g_acc[(k0 + 2) * ROWW + g], v2);
        }
    }
    {
        float a0 = wred(A0), a1 = wred(A1), a2 = wred(A2);
        if (lane == 0) {
            atomicAdd(&g_acc[(k0    ) * ROWW + KK], a0);
            atomicAdd(&g_acc[(k0 + 1) * ROWW + KK], a1);
            atomicAdd(&g_acc[(k0 + 2) * ROWW + KK], a2);
        }
    }

    __threadfence();
    __syncthreads();
    if (tid == 0)
        s_last = (atomicAdd(&g_ctr, 1) == (int)gridDim.x - 1) ? 1 : 0;
    __syncthreads();
    if (!s_last) return;
    __threadfence();

    // ---- last CTA: finalize ----
    for (int e = tid; e < NENT; e += TPB) {
        s_red[e] = __ldcg(&g_acc[e]);
        g_acc[e] = 0.0f;                 // reset for next replay
    }
    __syncthreads();

    int G = GMAX;
    if (gpn != nullptr) {
        const int gi = gpn[0];
        if (gi >= 1 && gi <= GMAX) G = gi;
        else {
            const float gfv = __int_as_float(gi);
            if (gfv >= 1.0f && gfv <= (float)GMAX && gfv == floorf(gfv))
                G = (int)gfv;
        }
    }

    __shared__ int   m_[KK];
    __shared__ float val[KK];
    __shared__ int   bestk[KK];

    if (tid < KK) {   // argmax_g S == argmin_g ce (first occurrence, strict >)
        int   best = 0;
        float bv   = s_red[tid * ROWW + 0];
        for (int g = 1; g < G; g++) {
            const float v = s_red[tid * ROWW + g];
            if (v > bv) { bv = v; best = g; }
        }
        m_[tid]  = best;
        val[tid] = s_red[tid * ROWW + KK] + bv;  // larger == smaller ce_val
    }
    __syncthreads();

    if (tid == 0) {
        int maxi = 0;
        for (int k = 0; k < KK; k++) if (m_[k] > maxi) maxi = m_[k];
        maxi += 1;
        for (int g = 0; g < G; g++) {
            float bb = -3.4e38f;
            int   bk = -1;
            for (int k = 0; k < KK; k++)
                if (m_[k] == g && val[k] > bb) { bb = val[k]; bk = k; }
            bestk[g] = bk;
        }
        for (int k = 0; k < KK; k++)
            out[k] = (float)((bestk[m_[k]] == k) ? m_[k] : maxi);
        g_ctr = 0;
    }
}

extern "C" void kernel_launch(void* const* d_in, const int* in_sizes, int n_in,
                              void* d_out, int out_size)
{
    int scalar_idx = -1;
    for (int i = 0; i < n_in; i++)
        if (in_sizes[i] == 1) { scalar_idx = i; break; }

    int big[2] = {-1, -1};
    int nb = 0;
    for (int i = 0; i < n_in && nb < 2; i++)
        if (i != scalar_idx) big[nb++] = i;

    const void* A   = d_in[big[0]];
    const void* B   = d_in[big[1]];
    const int*  gpn = (scalar_idx >= 0) ? (const int*)d_in[scalar_idx] : nullptr;

    const int bigsize = in_sizes[big[0]];
    int N    = bigsize / KK;
    if (N > MAXN) N = MAXN;              // static scratch bound (dataset: 230400)
    int GMAX = (N > 0) ? (bigsize / N) : KK;
    if (GMAX > KK) GMAX = KK;
    if (GMAX < 1)  GMAX = 1;

    pack_kernel<<<296, 256>>>(A, B, N, GMAX);
    match_kernel<<<NCTA, TPB>>>(A, B, gpn, (float*)d_out, N, GMAX);
}

// round 8
// speedup vs baseline: 1.3967x; 1.3967x over previous
#include <cuda_runtime.h>
#include <cstdint>

// MatchSegmentation, single fused kernel.
// matching = argmax_g S[k,g] (log2-space CE, monotone rescale); greedy dedup.
// 3-stage cp.async ring; gt converted int->float in smem once per tile;
// inner loop = LDS gv + 3 FMA per g. Per-warp reduce -> atomicAdd; last CTA
// finalizes (argmax + dedup) and resets state for graph replay.

#define KK   21            // predicted segments (== out_size)
#define EPSF 1e-6f
#define PIX  128           // pixels per tile
#define TPB  224           // 7 warps: warp w owns k in {3w,3w+1,3w+2}
#define NBLK 296           // 2 CTAs/SM on 148 SMs
#define NST  3             // pipeline stages
#define ROWW (KK+1)
#define NENT (KK*ROWW)     // 462

__device__ float g_acc[NENT];   // zero at load; last CTA re-zeros each run
__device__ int   g_ctr;

// gt_instance is int32 0/1; uniform(0,1) float bits are never <= 1.
__device__ __forceinline__ bool looks_like_gt(const void* p) {
    const unsigned* u = (const unsigned*)p;
    bool r = true;
#pragma unroll
    for (int i = 0; i < 64; i++) r = r && (u[i] <= 1u);
    return r;
}

__device__ __forceinline__ void cp16(void* sdst, const void* gsrc) {
    uint32_t sa = (uint32_t)__cvta_generic_to_shared(sdst);
    asm volatile("cp.async.cg.shared.global [%0], [%1], 16;" :: "r"(sa), "l"(gsrc));
}
__device__ __forceinline__ void cp_commit() { asm volatile("cp.async.commit_group;"); }
__device__ __forceinline__ void cp_wait1()  { asm volatile("cp.async.wait_group 1;"); }

__device__ __forceinline__ float wred(float v) {
    v += __shfl_down_sync(0xffffffffu, v, 16);
    v += __shfl_down_sync(0xffffffffu, v, 8);
    v += __shfl_down_sync(0xffffffffu, v, 4);
    v += __shfl_down_sync(0xffffffffu, v, 2);
    v += __shfl_down_sync(0xffffffffu, v, 1);
    return v;
}

__global__ __launch_bounds__(TPB, 2)
void match_kernel(const void* __restrict__ bigA, const void* __restrict__ bigB,
                  const int* __restrict__ gpn, float* __restrict__ out,
                  int N, int GMAX)
{
    const bool a_is_gt = looks_like_gt(bigA);
    const float* __restrict__ seg = (const float*)(a_is_gt ? bigB : bigA);
    const int*   __restrict__ gt  = (const int*)  (a_is_gt ? bigA : bigB);

    __shared__ float s_seg[NST][PIX * KK];  // [px][k]  10.5KB/stage
    __shared__ float s_gt [NST][KK * PIX];  // [g][px]  10.5KB/stage (int->float in place)
    __shared__ float s_red[NENT];
    __shared__ int   s_last;

    const int tid  = threadIdx.x;
    const int lane = tid & 31;
    const int k0   = (tid >> 5) * 3;
    const long long NKll = (long long)N * KK;

    float S0[KK], S1[KK], S2[KK];
    float A0 = 0.f, A1 = 0.f, A2 = 0.f;
#pragma unroll
    for (int g = 0; g < KK; g++) { S0[g] = 0.f; S1[g] = 0.f; S2[g] = 0.f; }

    // rows g >= GMAX stay float 0 forever (loads/convert touch only g < GMAX)
    if (GMAX < KK) {
        for (int i = tid; i < (KK - GMAX) * PIX; i += TPB) {
            const int g = GMAX + i / PIX, c = i % PIX;
#pragma unroll
            for (int b = 0; b < NST; b++) s_gt[b][g * PIX + c] = 0.0f;
        }
        __syncthreads();
    }

    const int  ntiles  = (N + PIX - 1) / PIX;
    const bool fastN   = ((N & 3) == 0);

    // Issue loads for tile index `it` (global tile = blockIdx.x + it*gridDim.x)
    auto load_tile = [&](int it) {
        const int t = blockIdx.x + it * gridDim.x;
        if (t < ntiles) {
            const int       b    = it % NST;
            const int       base = t * PIX;
            const long long tb   = (long long)t * (PIX * KK);
            if (fastN && base + PIX <= N) {
#pragma unroll
                for (int j = 0; j < 3; j++) {            // 672 float4 of seg
                    const int i = tid + j * TPB;
                    cp16(&s_seg[b][i * 4], seg + tb + i * 4);
                }
#pragma unroll
                for (int j = 0; j < 3; j++) {            // GMAX*32 int4 of gt
                    const int s = tid + j * TPB;
                    if (s < GMAX * 32) {
                        const int g = s >> 5, c = s & 31;
                        cp16((int*)s_gt[b] + g * PIX + c * 4,
                             gt + (long long)g * N + base + c * 4);
                    }
                }
            } else {                                     // generic tail
                for (int i = tid; i < PIX * KK; i += TPB) {
                    const long long idx = tb + i;
                    s_seg[b][i] = (idx < NKll) ? seg[idx] : 0.5f;  // pad: d=0
                }
                for (int s = tid; s < GMAX * PIX; s += TPB) {
                    const int g = s / PIX, c = s % PIX, p = base + c;
                    ((int*)s_gt[b])[g * PIX + c] = (p < N) ? gt[(long long)g * N + p] : 0;
                }
            }
        }
        cp_commit();   // always commit: keeps wait_group accounting aligned
    };

    const int myntiles = (ntiles > (int)blockIdx.x)
                       ? (ntiles - blockIdx.x + gridDim.x - 1) / gridDim.x : 0;

    load_tile(0);
    load_tile(1);

    for (int it = 0; it < myntiles; it++) {
        const int buf = it % NST;

        cp_wait1();          // tile it resident (<=1 younger group pending)
        __syncthreads();     // smem visible; prior compute on ring buffer done

        load_tile(it + 2);   // issue 2-ahead into the just-freed buffer

        // convert this tile's gt ints -> floats in place (int4 granularity)
        {
            const int n4 = GMAX * 32;
            for (int i = tid; i < n4; i += TPB) {
                int4 v = ((int4*)s_gt[buf])[i];
                float4 f = make_float4((float)v.x, (float)v.y,
                                       (float)v.z, (float)v.w);
                ((float4*)s_gt[buf])[i] = f;
            }
        }
        __syncthreads();     // converted floats visible to all warps

#pragma unroll
        for (int q = 0; q < 4; q++) {
            const int px = q * 32 + lane;
            const int pb = px * KK;
            float d0, d1, d2;
            {
                const float s  = s_seg[buf][pb + k0];
                const float l1 = __log2f(1.0f - s + EPSF);
                d0 = __log2f(s + EPSF) - l1;  A0 += l1;
            }
            {
                const float s  = s_seg[buf][pb + k0 + 1];
                const float l1 = __log2f(1.0f - s + EPSF);
                d1 = __log2f(s + EPSF) - l1;  A1 += l1;
            }
            {
                const float s  = s_seg[buf][pb + k0 + 2];
                const float l1 = __log2f(1.0f - s + EPSF);
                d2 = __log2f(s + EPSF) - l1;  A2 += l1;
            }
#pragma unroll
            for (int g = 0; g < KK; g++) {
                const float gv = s_gt[buf][g * PIX + px];  // stride-1: no conflicts
                S0[g] = fmaf(gv, d0, S0[g]);
                S1[g] = fmaf(gv, d1, S1[g]);
                S2[g] = fmaf(gv, d2, S2[g]);
            }
        }
    }

    // ---- warp reduce (lanes = pixels) -> atomic accumulate ----
#pragma unroll
    for (int g = 0; g < KK; g++) {
        float v0 = wred(S0[g]), v1 = wred(S1[g]), v2 = wred(S2[g]);
        if (lane == 0) {
            atomicAdd(&g_acc[(k0    ) * ROWW + g], v0);
            atomicAdd(&g_acc[(k0 + 1) * ROWW + g], v1);
            atomicAdd(&g_acc[(k0 + 2) * ROWW + g], v2);
        }
    }
    {
        float a0 = wred(A0), a1 = wred(A1), a2 = wred(A2);
        if (lane == 0) {
            atomicAdd(&g_acc[(k0    ) * ROWW + KK], a0);
            atomicAdd(&g_acc[(k0 + 1) * ROWW + KK], a1);
            atomicAdd(&g_acc[(k0 + 2) * ROWW + KK], a2);
        }
    }

    __threadfence();
    __syncthreads();
    if (tid == 0)
        s_last = (atomicAdd(&g_ctr, 1) == (int)gridDim.x - 1) ? 1 : 0;
    __syncthreads();
    if (!s_last) return;
    __threadfence();

    // ---- last CTA: finalize ----
    for (int e = tid; e < NENT; e += TPB) {
        s_red[e] = __ldcg(&g_acc[e]);
        g_acc[e] = 0.0f;                 // reset for next graph replay
    }
    __syncthreads();

    int G = GMAX;
    if (gpn != nullptr) {
        const int gi = gpn[0];
        if (gi >= 1 && gi <= GMAX) G = gi;
        else {
            const float gfv = __int_as_float(gi);
            if (gfv >= 1.0f && gfv <= (float)GMAX && gfv == floorf(gfv))
                G = (int)gfv;
        }
    }

    __shared__ int   m_[KK];
    __shared__ float val[KK];
    __shared__ int   bestk[KK];

    if (tid < KK) {   // argmax_g S == argmin_g ce (first occurrence, strict >)
        int   best = 0;
        float bv   = s_red[tid * ROWW + 0];
        for (int g = 1; g < G; g++) {
            const float v = s_red[tid * ROWW + g];
            if (v > bv) { bv = v; best = g; }
        }
        m_[tid]  = best;
        val[tid] = s_red[tid * ROWW + KK] + bv;  // larger == smaller ce_val
    }
    __syncthreads();

    if (tid == 0) {
        int maxi = 0;
        for (int k = 0; k < KK; k++) if (m_[k] > maxi) maxi = m_[k];
        maxi += 1;
        for (int g = 0; g < G; g++) {
            float bb = -3.4e38f;
            int   bk = -1;
            for (int k = 0; k < KK; k++)
                if (m_[k] == g && val[k] > bb) { bb = val[k]; bk = k; }
            bestk[g] = bk;
        }
        for (int k = 0; k < KK; k++)
            out[k] = (float)((bestk[m_[k]] == k) ? m_[k] : maxi);
        g_ctr = 0;
    }
}

extern "C" void kernel_launch(void* const* d_in, const int* in_sizes, int n_in,
                              void* d_out, int out_size)
{
    int scalar_idx = -1;
    for (int i = 0; i < n_in; i++)
        if (in_sizes[i] == 1) { scalar_idx = i; break; }

    int big[2] = {-1, -1};
    int nb = 0;
    for (int i = 0; i < n_in && nb < 2; i++)
        if (i != scalar_idx) big[nb++] = i;

    const void* A   = d_in[big[0]];
    const void* B   = d_in[big[1]];
    const int*  gpn = (scalar_idx >= 0) ? (const int*)d_in[scalar_idx] : nullptr;

    const int bigsize = in_sizes[big[0]];
    int N    = bigsize / KK;
    int GMAX = (N > 0) ? (bigsize / N) : KK;
    if (GMAX > KK) GMAX = KK;
    if (GMAX < 1)  GMAX = 1;

    match_kernel<<<NBLK, TPB>>>(A, B, gpn, (float*)d_out, N, GMAX);
}